// round 14
// baseline (speedup 1.0000x reference)
#include <cuda_runtime.h>
#include <cuda_fp16.h>
#include <cstdint>
#include <math.h>

#define N_NODES 8192
#define F_DIM   256
#define ALPHA   0.2f
#define M_CTA   64
#define KT      64
#define NTILES  (N_NODES / KT)     // 128

// ---------------- scratch (device globals; no allocation allowed) ------------
__device__ float  g_Wh[N_NODES * F_DIM];      // 8 MB fp32
__device__ __half g_Wh_h[N_NODES * F_DIM];    // 4 MB fp16
__device__ float  g_S1[N_NODES];
__device__ float  g_S2[N_NODES];
__device__ float  g_E2[N_NODES];
__device__ float  g_F2[N_NODES];

// ---------------- helpers ----------------------------------------------------
__device__ __forceinline__ uint32_t smem_u32(const void* p) {
    uint32_t a;
    asm("{ .reg .u64 t; cvta.to.shared.u64 t, %1; cvt.u32.u64 %0, t; }"
        : "=r"(a) : "l"(p));
    return a;
}
__device__ __forceinline__ void ldsm_x4(uint32_t* r, uint32_t addr) {
    asm volatile("ldmatrix.sync.aligned.m8n8.x4.shared.b16 {%0,%1,%2,%3}, [%4];"
                 : "=r"(r[0]), "=r"(r[1]), "=r"(r[2]), "=r"(r[3]) : "r"(addr));
}
__device__ __forceinline__ void ldsm_x4_t(uint32_t* r, uint32_t addr) {
    asm volatile("ldmatrix.sync.aligned.m8n8.x4.trans.shared.b16 {%0,%1,%2,%3}, [%4];"
                 : "=r"(r[0]), "=r"(r[1]), "=r"(r[2]), "=r"(r[3]) : "r"(addr));
}
__device__ __forceinline__ void mma_f16(float* c, const uint32_t* a, const uint32_t* b) {
    asm volatile(
        "mma.sync.aligned.m16n8k16.row.col.f32.f16.f16.f32 "
        "{%0,%1,%2,%3}, {%4,%5,%6,%7}, {%8,%9}, {%0,%1,%2,%3};"
        : "+f"(c[0]), "+f"(c[1]), "+f"(c[2]), "+f"(c[3])
        : "r"(a[0]), "r"(a[1]), "r"(a[2]), "r"(a[3]), "r"(b[0]), "r"(b[1]));
}
__device__ __forceinline__ void cp16(uint32_t dst, const void* src) {
    asm volatile("cp.async.cg.shared.global [%0], [%1], 16;"
                 :: "r"(dst), "l"(src) : "memory");
}
#define CP_COMMIT() asm volatile("cp.async.commit_group;" ::: "memory")
#define CP_WAIT0()  asm volatile("cp.async.wait_group 0;" ::: "memory")
#define CP_WAIT1()  asm volatile("cp.async.wait_group 1;" ::: "memory")

// split f32 -> (hi, lo) half2 pair packed as uint32
__device__ __forceinline__ void split2(float x, float y, uint32_t& hi, uint32_t& lo) {
    __half2 h = __floats2half2_rn(x, y);
    __half2 l = __floats2half2_rn(x - __low2float(h), y - __high2float(h));
    hi = *(uint32_t*)&h;
    lo = *(uint32_t*)&l;
}

// ============================================================================
// Kernel 1: Wh = h @ W + b on tensor cores (fp16 hi/lo split, 3 products)
// CTA: 128x128, K=256 in 8 tiles of 32; 256 thr (8 warps: 2M x 4N), warp 64x32
// Emits g_Wh fp32 and g_Wh_h fp16.
// ============================================================================
#define W1_APITCH 80     // bytes: 32 halves + 8 pad
#define W1_BPITCH 272    // bytes: 128 halves + 8 pad

__global__ __launch_bounds__(256) void k_wh_gemm(const float* __restrict__ h,
                                                 const float* __restrict__ W,
                                                 const float* __restrict__ b) {
    __shared__ __align__(16) __half sAhi[128 * 40];
    __shared__ __align__(16) __half sAlo[128 * 40];
    __shared__ __align__(16) __half sBhi[32 * 136];
    __shared__ __align__(16) __half sBlo[32 * 136];

    const int tid = threadIdx.x;
    const int wid = tid >> 5, lane = tid & 31;
    const int i0 = blockIdx.x * 128;
    const int n0 = blockIdx.y * 128;
    const int m0w = (wid & 1) * 64;
    const int n0w = (wid >> 1) * 32;

    const uint32_t aHiB = smem_u32(sAhi), aLoB = smem_u32(sAlo);
    const uint32_t bHiB = smem_u32(sBhi), bLoB = smem_u32(sBlo);

    // staging roles
    const int arow = tid >> 1, acg = (tid & 1) * 16;     // A: 2 thr/row, 16 cols each
    const int brow = tid >> 3, bcg = (tid & 7) * 16;     // B: 8 thr/row, 16 cols each

    float acc[4][4][4];
#pragma unroll
    for (int mf = 0; mf < 4; mf++)
#pragma unroll
        for (int nf = 0; nf < 4; nf++)
#pragma unroll
            for (int c = 0; c < 4; c++) acc[mf][nf][c] = 0.f;

    const int lr = lane & 15;
    const int lc = lane >> 4;

    for (int kt = 0; kt < 8; kt++) {
        const int k0 = kt * 32;
        // ---- gmem loads to regs ----
        float4 av[4], bv[4];
#pragma unroll
        for (int q = 0; q < 4; q++) {
            av[q] = *(const float4*)&h[(size_t)(i0 + arow) * F_DIM + k0 + acg + q * 4];
            bv[q] = *(const float4*)&W[(size_t)(k0 + brow) * F_DIM + n0 + bcg + q * 4];
        }
        __syncthreads();   // previous tile fully consumed

        // ---- convert + STS (hi/lo split) ----
        {
            uint32_t ph[8], pl[8];
#pragma unroll
            for (int q = 0; q < 4; q++) {
                split2(av[q].x, av[q].y, ph[2 * q], pl[2 * q]);
                split2(av[q].z, av[q].w, ph[2 * q + 1], pl[2 * q + 1]);
            }
            __half* dst = &sAhi[arow * 40 + acg];
            *(uint4*)dst       = make_uint4(ph[0], ph[1], ph[2], ph[3]);
            *(uint4*)(dst + 8) = make_uint4(ph[4], ph[5], ph[6], ph[7]);
            __half* dstl = &sAlo[arow * 40 + acg];
            *(uint4*)dstl       = make_uint4(pl[0], pl[1], pl[2], pl[3]);
            *(uint4*)(dstl + 8) = make_uint4(pl[4], pl[5], pl[6], pl[7]);
#pragma unroll
            for (int q = 0; q < 4; q++) {
                split2(bv[q].x, bv[q].y, ph[2 * q], pl[2 * q]);
                split2(bv[q].z, bv[q].w, ph[2 * q + 1], pl[2 * q + 1]);
            }
            __half* bdst = &sBhi[brow * 136 + bcg];
            *(uint4*)bdst       = make_uint4(ph[0], ph[1], ph[2], ph[3]);
            *(uint4*)(bdst + 8) = make_uint4(ph[4], ph[5], ph[6], ph[7]);
            __half* bdstl = &sBlo[brow * 136 + bcg];
            *(uint4*)bdstl       = make_uint4(pl[0], pl[1], pl[2], pl[3]);
            *(uint4*)(bdstl + 8) = make_uint4(pl[4], pl[5], pl[6], pl[7]);
        }
        __syncthreads();

        // ---- MMA: 2 k16 steps, 3 products (hh, hl, lh) ----
#pragma unroll
        for (int k16 = 0; k16 < 2; k16++) {
            const uint32_t acol = (k16 * 16 + 8 * lc) * 2;
            uint32_t ahh[4][4], ahl[4][4], bbh[2][4], bbl[2][4];
#pragma unroll
            for (int mf = 0; mf < 4; mf++) {
                const uint32_t aoff = (m0w + mf * 16 + lr) * W1_APITCH + acol;
                ldsm_x4(ahh[mf], aHiB + aoff);
                ldsm_x4(ahl[mf], aLoB + aoff);
            }
#pragma unroll
            for (int nh = 0; nh < 2; nh++) {
                const uint32_t boff = (k16 * 16 + lr) * W1_BPITCH +
                                      (n0w + nh * 16 + 8 * lc) * 2;
                ldsm_x4_t(bbh[nh], bHiB + boff);
                ldsm_x4_t(bbl[nh], bLoB + boff);
            }
#pragma unroll
            for (int mf = 0; mf < 4; mf++)
#pragma unroll
                for (int nf = 0; nf < 4; nf++) {
                    float* c = acc[mf][nf];
                    const uint32_t* bh = &bbh[nf >> 1][(nf & 1) * 2];
                    mma_f16(c, ahh[mf], bh);
                    mma_f16(c, ahl[mf], bh);
                    mma_f16(c, ahh[mf], &bbl[nf >> 1][(nf & 1) * 2]);
                }
        }
    }

    // ---- epilogue: bias + store fp32 and fp16 ----
#pragma unroll
    for (int mf = 0; mf < 4; mf++) {
        const int r0 = i0 + m0w + mf * 16 + (lane >> 2);
#pragma unroll
        for (int nf = 0; nf < 4; nf++) {
            const int col = n0 + n0w + nf * 8 + (lane & 3) * 2;
            const float2 bia = *(const float2*)&b[col];
            float* c = acc[mf][nf];
            float2 v0 = {c[0] + bia.x, c[1] + bia.y};
            float2 v1 = {c[2] + bia.x, c[3] + bia.y};
            *(float2*)&g_Wh[(size_t)r0 * F_DIM + col] = v0;
            *(float2*)&g_Wh[(size_t)(r0 + 8) * F_DIM + col] = v1;
            __half2 h0 = __floats2half2_rn(v0.x, v0.y);
            __half2 h1 = __floats2half2_rn(v1.x, v1.y);
            *(uint32_t*)&g_Wh_h[(size_t)r0 * F_DIM + col] = *(uint32_t*)&h0;
            *(uint32_t*)&g_Wh_h[(size_t)(r0 + 8) * F_DIM + col] = *(uint32_t*)&h1;
        }
    }
}

// ============================================================================
// Kernel 2: per-node scores + exp tables
// ============================================================================
__global__ __launch_bounds__(256) void k_scores(const float* __restrict__ a) {
    const int row  = blockIdx.x * 8 + (threadIdx.x >> 5);
    const int lane = threadIdx.x & 31;
    float acc1 = 0.f, acc2 = 0.f;
#pragma unroll
    for (int t = 0; t < 8; t++) {
        const int k = lane + t * 32;
        const float w = g_Wh[(size_t)row * F_DIM + k];
        acc1 += w * a[k];
        acc2 += w * a[F_DIM + k];
    }
#pragma unroll
    for (int off = 16; off > 0; off >>= 1) {
        acc1 += __shfl_xor_sync(0xffffffffu, acc1, off);
        acc2 += __shfl_xor_sync(0xffffffffu, acc2, off);
    }
    if (lane == 0) {
        g_S1[row] = acc1;
        g_S2[row] = acc2;
        g_E2[row] = expf(acc2);
        g_F2[row] = expf(ALPHA * acc2);
    }
}

// ============================================================================
// Kernel 3: fused masked-softmax AV GEMM (UNCHANGED from R12 best)
// CTA: 64 rows x 256 feats, 1024 thr (32 warps: 4M x 8N), warp tile 16x32
// Triple-buffered B (cp.async, distance 2), one barrier/tile.
// ============================================================================
#define A_PITCH 144
#define B_PITCH 528
#define ABUF(b)   ((b) * 9216)             // A[64][64] f16, pitch 144 (x2)
#define BBUF(b)   (18432 + (b) * 33792)    // B[64][256] f16, pitch 528 (x3)
#define SMEM_DYN  119808

__global__ __launch_bounds__(1024, 1) void k_attn_av(const int* __restrict__ adj,
                                                     float* __restrict__ out) {
    extern __shared__ __align__(16) char dyn[];
    __shared__ float sDsum[M_CTA][16];
    __shared__ float sInv[M_CTA];

    const int tid = threadIdx.x;
    const int wid = tid >> 5, lane = tid & 31;
    const int i0 = blockIdx.x * M_CTA;
    const uint32_t sBase = smem_u32(dyn);

    // roles
    const int bm = tid >> 4;            // weight-build row 0..63
    const int bj = (tid & 15) * 4;      // j-chunk (4 j's within KT=64)
    const int cj = tid >> 4;            // cp.async j row 0..63
    const int cc = (tid & 15) * 32;     // cp.async byte offset in 512B row
    const int m0w = (wid & 3) * 16;     // warp M origin (4 M-warps x 16)
    const int n0w = (wid >> 2) * 32;    // warp N origin (8 N-warps x 32)

    const float s1 = g_S1[i0 + bm];
    const float e1 = expf(s1), f1 = expf(ALPHA * s1), t1 = -s1;
    float ds = 0.f;

    float acc[4][4];                    // [nf][4]
#pragma unroll
    for (int nf = 0; nf < 4; nf++)
#pragma unroll
        for (int c = 0; c < 4; c++) acc[nf][c] = 0.f;

    auto stageB = [&](int t) {
        const size_t gb = ((size_t)(t * KT + cj) * F_DIM) * 2 + cc;
        const uint32_t sm = sBase + BBUF(t % 3) + cj * B_PITCH + cc;
        cp16(sm,      (const char*)g_Wh_h + gb);
        cp16(sm + 16, (const char*)g_Wh_h + gb + 16);
        CP_COMMIT();
    };
    auto buildA = [&](int buf, int4 adjv, float4 s2v, float4 e2v, float4 f2v) {
        const int   ai[4]  = {adjv.x, adjv.y, adjv.z, adjv.w};
        const float s2a[4] = {s2v.x, s2v.y, s2v.z, s2v.w};
        const float e2a[4] = {e2v.x, e2v.y, e2v.z, e2v.w};
        const float f2a[4] = {f2v.x, f2v.y, f2v.z, f2v.w};
        float wv[4];
#pragma unroll
        for (int c = 0; c < 4; c++) {
            float w = 0.f;
            if (ai[c] > 0) w = (s2a[c] > t1) ? e1 * e2a[c] : f1 * f2a[c];
            wv[c] = w;
        }
        uint32_t p[2];
#pragma unroll
        for (int q = 0; q < 2; q++) {
            __half2 hq = __floats2half2_rn(wv[2 * q], wv[2 * q + 1]);
            p[q] = *(uint32_t*)&hq;
            const float2 dq = __half22float2(hq);
            ds += dq.x + dq.y;                 // denominator == quantized numerator
        }
        *(uint2*)(dyn + ABUF(buf) + bm * A_PITCH + bj * 2) = make_uint2(p[0], p[1]);
    };

    const int lr = lane & 15;
    const int lc = lane >> 4;

    {
        stageB(0);
        stageB(1);
        const size_t ab = (size_t)(i0 + bm) * N_NODES + bj;
        buildA(0, *(const int4*)&adj[ab],
               *(const float4*)&g_S2[bj], *(const float4*)&g_E2[bj],
               *(const float4*)&g_F2[bj]);
    }

    int4 adjv; float4 s2v, e2v, f2v;
    for (int t = 0; t < NTILES; t++) {
        const bool more = (t + 1 < NTILES);

        if (more) {
            const int jn = (t + 1) * KT;
            adjv = *(const int4*)&adj[(size_t)(i0 + bm) * N_NODES + jn + bj];
            s2v = *(const float4*)&g_S2[jn + bj];
            e2v = *(const float4*)&g_E2[jn + bj];
            f2v = *(const float4*)&g_F2[jn + bj];
        }

        CP_WAIT1();
        __syncthreads();   // A(t), B(t) visible; all warps past MMA(t-1)

        if (t + 2 < NTILES) stageB(t + 2);
        else CP_COMMIT();

        const uint32_t aBase = sBase + ABUF(t & 1);
        const uint32_t bBase = sBase + BBUF(t % 3);
#pragma unroll
        for (int kk = 0; kk < 4; kk++) {
            const int k16 = (kk + wid) & 3;
            const int k0 = k16 * 16;
            uint32_t ah[4], bb[2][4];
            ldsm_x4(ah, aBase + (m0w + lr) * A_PITCH + (k0 + 8 * lc) * 2);
#pragma unroll
            for (int nh = 0; nh < 2; nh++)
                ldsm_x4_t(bb[nh], bBase + (k0 + lr) * B_PITCH + (n0w + nh * 16 + 8 * lc) * 2);
#pragma unroll
            for (int nf = 0; nf < 4; nf++)
                mma_f16(acc[nf], ah, &bb[nf >> 1][(nf & 1) * 2]);
        }

        if (more) buildA((t + 1) & 1, adjv, s2v, e2v, f2v);
    }

    // ---- denominator reduce ----
    __syncthreads();
    sDsum[bm][tid & 15] = ds;
    __syncthreads();
    if (tid < M_CTA) {
        float s = 0.f;
#pragma unroll
        for (int g = 0; g < 16; g++) s += sDsum[tid][g];
        sInv[tid] = 1.0f / s;
    }
    __syncthreads();

    // ---- epilogue: normalize + store ----
    {
        const int r0 = m0w + (lane >> 2);
        const float inv0 = sInv[r0];
        const float inv1 = sInv[r0 + 8];
#pragma unroll
        for (int nf = 0; nf < 4; nf++) {
            const int col = n0w + nf * 8 + (lane & 3) * 2;
            float2 v0 = {acc[nf][0] * inv0, acc[nf][1] * inv0};
            float2 v1 = {acc[nf][2] * inv1, acc[nf][3] * inv1};
            *(float2*)&out[(size_t)(i0 + r0) * F_DIM + col] = v0;
            *(float2*)&out[(size_t)(i0 + r0 + 8) * F_DIM + col] = v1;
        }
    }
}

// ============================================================================
extern "C" void kernel_launch(void* const* d_in, const int* in_sizes, int n_in,
                              void* d_out, int out_size) {
    const float* h   = (const float*)d_in[0];
    const int*   adj = (const int*)d_in[1];
    const float* Ww  = (const float*)d_in[2];
    const float* Wb  = (const float*)d_in[3];
    const float* a   = (const float*)d_in[4];
    float* out = (float*)d_out;

    static int attr_done = 0;
    if (!attr_done) {
        cudaFuncSetAttribute(k_attn_av, cudaFuncAttributeMaxDynamicSharedMemorySize,
                             SMEM_DYN);
        attr_done = 1;
    }

    k_wh_gemm<<<dim3(N_NODES / 128, F_DIM / 128), 256>>>(h, Ww, Wb);
    k_scores<<<N_NODES / 8, 256>>>(a);
    k_attn_av<<<N_NODES / M_CTA, 1024, SMEM_DYN>>>(adj, out);
}